// round 11
// baseline (speedup 1.0000x reference)
#include <cuda_runtime.h>
#include <cuda_bf16.h>

#define F_DIM   35
#define T_PAD   512
#define LOG2E   1.4426950408889634f
#define LN2     0.6931471805599453f
#define CDEAD   (-(1 << 28))
#define DRIFT_T 48

__device__ float g_partials[1024];
__device__ int   g_count = 0;

__device__ __forceinline__ float ex2f(float x) {
    float r; asm("ex2.approx.ftz.f32 %0, %1;" : "=f"(r) : "f"(x)); return r;
}
__device__ __forceinline__ float lg2f(float x) {
    float r; asm("lg2.approx.ftz.f32 %0, %1;" : "=f"(r) : "f"(x)); return r;
}
__device__ __forceinline__ float pow2i(int e) {   // 2^e, e in [-127,128]
    return __uint_as_float((unsigned)(127 + e) << 23);
}

// One WARP per (b,f) task; thread owns 4 state-pairs. Linear-domain CTC with
// per-thread power-of-2 refs. The per-window EXACT prefix-max-with-drift scan
// is computed at radix 8: 7 parallel shfls of C, then 3 parallel shfls of the
// stage-1 maxima — serial depth 2 shfl-latencies instead of 5. Rp (= neighbor's
// scan result) is reconstructed in-lane from the same shfl outputs, and aoRaw
// is rebased via a carried Rprev register — no serial tail shfls. Result is
// bit-identical to the 5-stage scan, so all overflow/FTZ invariants hold.
__global__ __launch_bounds__(128, 1) void sctc_warp_kernel(
    const float* __restrict__ logits,        // (B,T,F)
    const float* __restrict__ blank_logit,   // (1,)
    const int*   __restrict__ targets,       // (B,S,F)
    const int*   __restrict__ input_lengths, // (B,)
    const int*   __restrict__ target_lengths,// (B,)
    float* __restrict__ out,
    int B, int T, int S, int nTasks)
{
    __shared__ float4 P4[4][T_PAD];    // per-warp {q0, q1, pb, pad}
    __shared__ float  AeF[4][128];
    __shared__ float  AoF[4][128];
    __shared__ int    RF[4][32];

    const int tid  = threadIdx.x;
    const int lane = tid & 31;
    const int w    = tid >> 5;
    int  task = blockIdx.x * 4 + w;
    bool live = (task < nTasks);
    if (!live) task = 0;
    const int b = task / F_DIM;
    const int f = task - b * F_DIM;

    const float ub = blank_logit[0] * LOG2E;
    float4* Pw = P4[w];

    // ---- linear 3-class softmax, packed ----
    for (int t = lane; t < T; t += 32) {
        float u  = logits[(b * T + t) * F_DIM + f] * LOG2E;
        float m  = fmaxf(fabsf(u), ub);
        float s0 = ex2f(-u - m);
        float s1 = ex2f( u - m);
        float s2 = ex2f(ub - m);
        float iv = 1.0f / (s0 + s1 + s2);
        Pw[t] = make_float4(s0 * iv, s1 * iv, s2 * iv, 0.0f);
    }

    // ---- per-pair structure ----
    const int p0 = lane * 4;
    bool  labB[4];
    float skA[4];
    {
        const int base = b * S * F_DIM + f;
        int prev = (p0 >= 1 && p0 - 1 < S) ? targets[base + (p0 - 1) * F_DIM] : -1;
        #pragma unroll
        for (int i = 0; i < 4; ++i) {
            int p = p0 + i;
            int l = (p < S) ? targets[base + p * F_DIM] : 0;
            labB[i] = (l != 0);
            skA[i]  = (p >= 1 && p < S && l != prev) ? 1.0f : 0.0f;
            prev = l;
        }
    }
    __syncwarp();

    // ---- init at t=0 ----
    float ae0 = 0.f, ae1 = 0.f, ae2 = 0.f, ae3 = 0.f;
    float ao0 = 0.f, ao1 = 0.f, ao2 = 0.f, ao3 = 0.f;
    if (lane == 0) {
        float4 q = Pw[0];
        ae0 = q.z;
        ao0 = labB[0] ? q.y : q.x;
    }
    int   R     = 0;
    int   Rprev = 0;      // neighbor (lane-1) ref, carried
    float scIn  = 0.0f;
    float aoRaw = 0.0f;   // raw shfl of neighbor's ao3, in neighbor's scale
    const bool lz = (lane == 0);

    // One step, phase-batched. Lane 0's scIn is 0, so no lane select needed.
#define STEP(q4)                                                                \
    {                                                                           \
        float q0 = (q4).x, q1 = (q4).y, pb = (q4).z;                            \
        float t1 = aoRaw * scIn;                                                \
        float se0 = ae0 + t1;                                                   \
        float se1 = ae1 + ao0;                                                  \
        float se2 = ae2 + ao1;                                                  \
        float se3 = ae3 + ao2;                                                  \
        float so0 = ao0 + ae0;                                                  \
        float so1 = ao1 + ae1;                                                  \
        float so2 = ao2 + ae2;                                                  \
        float so3 = ao3 + ae3;                                                  \
        so3 = __fmaf_rn(skA[3], ao2, so3);                                      \
        float pl3 = labB[3] ? q1 : q0;                                          \
        float nao3 = so3 * pl3;                                                 \
        float aoN = __shfl_up_sync(0xffffffffu, nao3, 1);                       \
        so0 = __fmaf_rn(skA[0], t1,  so0);                                      \
        so1 = __fmaf_rn(skA[1], ao0, so1);                                      \
        so2 = __fmaf_rn(skA[2], ao1, so2);                                      \
        float pl0 = labB[0] ? q1 : q0;                                          \
        float pl1 = labB[1] ? q1 : q0;                                          \
        float pl2 = labB[2] ? q1 : q0;                                          \
        ae0 = se0 * pb; ae1 = se1 * pb; ae2 = se2 * pb; ae3 = se3 * pb;         \
        ao0 = so0 * pl0; ao1 = so1 * pl1; ao2 = so2 * pl2; ao3 = nao3;          \
        aoRaw = aoN;                                                            \
    }

    // Fresh-value normalize; EXACT prefix-max-with-drift scan at radix 8.
#define NORM()                                                                  \
    {                                                                           \
        float mv = fmaxf(fmaxf(fmaxf(ae0, ao0), fmaxf(ae1, ao1)),               \
                         fmaxf(fmaxf(ae2, ao2), fmaxf(ae3, ao3)));              \
        int C = (mv > 0.0f)                                                     \
              ? (R + (int)((__float_as_uint(mv) >> 23) & 255u) - 127)           \
              : CDEAD;                                                          \
        int cu1 = __shfl_up_sync(0xffffffffu, C, 1);                            \
        int cu2 = __shfl_up_sync(0xffffffffu, C, 2);                            \
        int cu3 = __shfl_up_sync(0xffffffffu, C, 3);                            \
        int cu4 = __shfl_up_sync(0xffffffffu, C, 4);                            \
        int cu5 = __shfl_up_sync(0xffffffffu, C, 5);                            \
        int cu6 = __shfl_up_sync(0xffffffffu, C, 6);                            \
        int cu7 = __shfl_up_sync(0xffffffffu, C, 7);                            \
        int N = C;                                                              \
        if (lane >= 1) N = max(N, cu1 - 1 * DRIFT_T);                           \
        if (lane >= 2) N = max(N, cu2 - 2 * DRIFT_T);                           \
        if (lane >= 3) N = max(N, cu3 - 3 * DRIFT_T);                           \
        if (lane >= 4) N = max(N, cu4 - 4 * DRIFT_T);                           \
        if (lane >= 5) N = max(N, cu5 - 5 * DRIFT_T);                           \
        if (lane >= 6) N = max(N, cu6 - 6 * DRIFT_T);                           \
        if (lane >= 7) N = max(N, cu7 - 7 * DRIFT_T);                           \
        int nu8  = __shfl_up_sync(0xffffffffu, N, 8);                           \
        int nu16 = __shfl_up_sync(0xffffffffu, N, 16);                          \
        int nu24 = __shfl_up_sync(0xffffffffu, N, 24);                          \
        int Rn = N;                                                             \
        if (lane >= 8)  Rn = max(Rn, nu8  -  8 * DRIFT_T);                      \
        if (lane >= 16) Rn = max(Rn, nu16 - 16 * DRIFT_T);                      \
        if (lane >= 24) Rn = max(Rn, nu24 - 24 * DRIFT_T);                      \
        int Rp;                                                                 \
        if (lz) Rp = Rn - 200;                                                  \
        else {                                                                  \
            Rp = cu1;                              /* i=1, drift 0 */           \
            if (lane >= 2) Rp = max(Rp, cu2 - 1 * DRIFT_T);                     \
            if (lane >= 3) Rp = max(Rp, cu3 - 2 * DRIFT_T);                     \
            if (lane >= 4) Rp = max(Rp, cu4 - 3 * DRIFT_T);                     \
            if (lane >= 5) Rp = max(Rp, cu5 - 4 * DRIFT_T);                     \
            if (lane >= 6) Rp = max(Rp, cu6 - 5 * DRIFT_T);                     \
            if (lane >= 7) Rp = max(Rp, cu7 - 6 * DRIFT_T);                     \
            if (lane >= 8)  Rp = max(Rp, nu8  -  7 * DRIFT_T);                  \
            if (lane >= 16) Rp = max(Rp, nu16 - 15 * DRIFT_T);                  \
            if (lane >= 24) Rp = max(Rp, nu24 - 23 * DRIFT_T);                  \
        }                                                                       \
        int d = Rp - Rn;                           /* <= 48, exact scan */      \
        scIn = (d < -127) ? 0.0f : pow2i(min(d, 127));                          \
        int sh = R - Rn;                                                        \
        int sa = max(-127, min(127, sh));                                       \
        int sb = max(-127, min(127, sh - sa));                                  \
        float fa = pow2i(sa), fb = pow2i(sb);                                   \
        ae0 = (ae0*fa)*fb; ae1 = (ae1*fa)*fb; ae2 = (ae2*fa)*fb; ae3 = (ae3*fa)*fb; \
        ao0 = (ao0*fa)*fb; ao1 = (ao1*fa)*fb; ao2 = (ao2*fa)*fb; ao3 = (ao3*fa)*fb; \
        int shp = Rprev - Rp;                      /* neighbor's rescale */     \
        int pa_ = max(-127, min(127, shp));                                     \
        int pb_ = max(-127, min(127, shp - pa_));                               \
        aoRaw = (aoRaw * pow2i(pa_)) * pow2i(pb_);                              \
        R = Rn; Rprev = Rp;                                                     \
    }

    // ---- initial full scan at t=0 (runs once; serial 5-stage is fine) ----
    {
        float mv = fmaxf(ae0, ao0);
        int C = (mv > 0.0f)
              ? (R + (int)((__float_as_uint(mv) >> 23) & 255u) - 127)
              : CDEAD;
        #pragma unroll
        for (int o = 1; o < 32; o <<= 1) {
            int cu = __shfl_up_sync(0xffffffffu, C, o);
            if (lane >= o) C = max(C, cu - DRIFT_T * o);
        }
        int Rn = C;
        int Rp = __shfl_up_sync(0xffffffffu, Rn, 1);
        if (lz) Rp = Rn - 200;
        int d = Rp - Rn;
        scIn = (d < -127) ? 0.0f : pow2i(min(d, 127));
        int sh = R - Rn;
        int sa = max(-127, min(127, sh));
        int sb = max(-127, min(127, sh - sa));
        float fa = pow2i(sa), fb = pow2i(sb);
        ae0 = (ae0*fa)*fb; ao0 = (ao0*fa)*fb;
        R = Rn; Rprev = Rp;
        aoRaw = __shfl_up_sync(0xffffffffu, ao3, 1);
    }

    const int Tin = input_lengths[b];
    int t = 1;

    // Steady state (R9 semantics: NORM after each 8-step window). The NEXT
    // window's 8 prob loads are issued BEFORE the norm so the LDS latency
    // drains underneath the scan's shfl chain.
    float4 q[8];
    bool have = (t + 8 <= Tin);
    if (have) {
        #pragma unroll
        for (int j = 0; j < 8; ++j) q[j] = Pw[t + j];
    }
    while (have) {
        #pragma unroll
        for (int j = 0; j < 8; ++j) STEP(q[j]);
        t += 8;
        have = (t + 8 <= Tin);
        if (have) {
            #pragma unroll
            for (int j = 0; j < 8; ++j) q[j] = Pw[t + j];
        }
        NORM();
    }
    for (; t < Tin; ++t) { float4 q4 = Pw[t]; STEP(q4); }  // <= 7 post-NORM steps

    // ---- spill finals; lane 0 finalizes this task ----
    AeF[w][p0 + 0] = ae0; AeF[w][p0 + 1] = ae1; AeF[w][p0 + 2] = ae2; AeF[w][p0 + 3] = ae3;
    AoF[w][p0 + 0] = ao0; AoF[w][p0 + 1] = ao1; AoF[w][p0 + 2] = ao2; AoF[w][p0 + 3] = ao3;
    RF[w][lane] = R;
    __syncwarp();

    if (lane == 0 && live) {
        int   Lt = target_lengths[b];
        float v1 = AeF[w][Lt];     int r1 = RF[w][Lt >> 2];
        float v2 = AoF[w][Lt - 1]; int r2 = RF[w][(Lt - 1) >> 2];
        int   Rm = max(r1, r2);
        float w1 = (r1 - Rm < -127) ? 0.0f : pow2i(r1 - Rm);
        float w2 = (r2 - Rm < -127) ? 0.0f : pow2i(r2 - Rm);
        float v  = v1 * w1 + v2 * w2;
        float ll2  = lg2f(v) + (float)Rm;
        float loss = -ll2 * LN2;
        if (!(loss <= 0.5e30f)) loss = 0.0f;   // zero_infinity (also nan/inf)
        g_partials[task] = loss / (float)Lt;
    }
    __syncthreads();

    // ---- fused deterministic reduction (last CTA) ----
    bool isLast = false;
    if (tid == 0) {
        __threadfence();
        int old = atomicAdd(&g_count, 1);
        isLast = (old == (int)gridDim.x - 1);
    }
    if (tid < 32) {
        int last = __shfl_sync(0xffffffffu, isLast ? 1 : 0, 0);
        if (last) {
            float sv = 0.0f;
            for (int j = lane; j < nTasks; j += 32) sv += g_partials[j];
            #pragma unroll
            for (int o = 16; o; o >>= 1) sv += __shfl_down_sync(0xffffffffu, sv, o);
            if (lane == 0) {
                out[0] = sv / (float)nTasks;
                g_count = 0;               // reset for next graph replay
            }
        }
    }
#undef STEP
#undef NORM
}

extern "C" void kernel_launch(void* const* d_in, const int* in_sizes, int n_in,
                              void* d_out, int out_size)
{
    const float* logits  = (const float*)d_in[0];
    const float* blankl  = (const float*)d_in[1];
    const int*   targets = (const int*)d_in[2];
    const int*   in_len  = (const int*)d_in[3];
    const int*   tg_len  = (const int*)d_in[4];

    const int B = in_sizes[3];
    const int T = in_sizes[0] / (B * F_DIM);
    const int S = in_sizes[2] / (B * F_DIM);
    const int nTasks = B * F_DIM;
    const int nblk   = (nTasks + 3) / 4;

    sctc_warp_kernel<<<nblk, 128>>>(logits, blankl, targets, in_len, tg_len,
                                    (float*)d_out, B, T, S, nTasks);
}

// round 13
// speedup vs baseline: 1.5354x; 1.5354x over previous
#include <cuda_runtime.h>
#include <cuda_bf16.h>

#define F_DIM   35
#define T_PAD   512
#define LOG2E   1.4426950408889634f
#define LN2     0.6931471805599453f
#define CDEAD   (-(1 << 28))
#define DRIFT_T 48

__device__ float g_partials[1024];
__device__ int   g_count = 0;

__device__ __forceinline__ float ex2f(float x) {
    float r; asm("ex2.approx.ftz.f32 %0, %1;" : "=f"(r) : "f"(x)); return r;
}
__device__ __forceinline__ float lg2f(float x) {
    float r; asm("lg2.approx.ftz.f32 %0, %1;" : "=f"(r) : "f"(x)); return r;
}
__device__ __forceinline__ float pow2i(int e) {   // 2^e, e in [-127,128]
    return __uint_as_float((unsigned)(127 + e) << 23);
}

// One WARP per (b,f) task; thread owns 4 state-pairs. Linear-domain CTC with
// per-thread power-of-2 refs, NORM every 8 frames (R9 semantics, verbatim).
// This revision ONLY reorders STEP: pair 3 (shfl producer) first, pair 0
// (shfl consumer, via the carried aoRaw) LAST — the ~32-cyc shfl latency is
// covered by ~24 instructions instead of ~14. Arithmetic is bit-identical.
__global__ __launch_bounds__(128, 1) void sctc_warp_kernel(
    const float* __restrict__ logits,        // (B,T,F)
    const float* __restrict__ blank_logit,   // (1,)
    const int*   __restrict__ targets,       // (B,S,F)
    const int*   __restrict__ input_lengths, // (B,)
    const int*   __restrict__ target_lengths,// (B,)
    float* __restrict__ out,
    int B, int T, int S, int nTasks)
{
    __shared__ float4 P4[4][T_PAD];    // per-warp {q0, q1, pb, pad}
    __shared__ float  AeF[4][128];
    __shared__ float  AoF[4][128];
    __shared__ int    RF[4][32];

    const int tid  = threadIdx.x;
    const int lane = tid & 31;
    const int w    = tid >> 5;
    int  task = blockIdx.x * 4 + w;
    bool live = (task < nTasks);
    if (!live) task = 0;
    const int b = task / F_DIM;
    const int f = task - b * F_DIM;

    const float ub = blank_logit[0] * LOG2E;
    float4* Pw = P4[w];

    // ---- linear 3-class softmax, packed ----
    for (int t = lane; t < T; t += 32) {
        float u  = logits[(b * T + t) * F_DIM + f] * LOG2E;
        float m  = fmaxf(fabsf(u), ub);
        float s0 = ex2f(-u - m);
        float s1 = ex2f( u - m);
        float s2 = ex2f(ub - m);
        float iv = 1.0f / (s0 + s1 + s2);
        Pw[t] = make_float4(s0 * iv, s1 * iv, s2 * iv, 0.0f);
    }

    // ---- per-pair structure ----
    const int p0 = lane * 4;
    bool  labB[4];
    float skA[4];
    {
        const int base = b * S * F_DIM + f;
        int prev = (p0 >= 1 && p0 - 1 < S) ? targets[base + (p0 - 1) * F_DIM] : -1;
        #pragma unroll
        for (int i = 0; i < 4; ++i) {
            int p = p0 + i;
            int l = (p < S) ? targets[base + p * F_DIM] : 0;
            labB[i] = (l != 0);
            skA[i]  = (p >= 1 && p < S && l != prev) ? 1.0f : 0.0f;
            prev = l;
        }
    }
    __syncwarp();

    // ---- init at t=0 ----
    float ae0 = 0.f, ae1 = 0.f, ae2 = 0.f, ae3 = 0.f;
    float ao0 = 0.f, ao1 = 0.f, ao2 = 0.f, ao3 = 0.f;
    if (lane == 0) {
        float4 q = Pw[0];
        ae0 = q.z;
        ao0 = labB[0] ? q.y : q.x;
    }
    int   R     = 0;
    float scIn  = 0.0f;
    float aoRaw = 0.0f;   // raw shfl of neighbor's ao3 (lane0: scIn==0 kills it)
    const bool lz = (lane == 0);

    // One step, reordered: pair 3 (shfl producer) FIRST, pair 0 (consumer of
    // the PREVIOUS step's shfl, via carried aoRaw) LAST. Same math as R9.
#define STEP(q4)                                                                \
    {                                                                           \
        float q0 = (q4).x, q1 = (q4).y, pb = (q4).z;                            \
        /* pair 3: producer of the cross-lane value */                          \
        float so3 = ao3 + ae3;                                                  \
        so3 = __fmaf_rn(skA[3], ao2, so3);                                      \
        float pl3 = labB[3] ? q1 : q0;                                          \
        float nao3 = so3 * pl3;                                                 \
        float aoN = __shfl_up_sync(0xffffffffu, nao3, 1);                       \
        float nae3 = (ae3 + ao2) * pb;                                          \
        /* pairs 2, 1 */                                                        \
        float se2 = ae2 + ao1;                                                  \
        float so2 = ao2 + ae2;                                                  \
        so2 = __fmaf_rn(skA[2], ao1, so2);                                      \
        float se1 = ae1 + ao0;                                                  \
        float so1 = ao1 + ae1;                                                  \
        so1 = __fmaf_rn(skA[1], ao0, so1);                                      \
        float pl2 = labB[2] ? q1 : q0;                                          \
        float pl1 = labB[1] ? q1 : q0;                                          \
        float nae2 = se2 * pb;                                                  \
        float nao2 = so2 * pl2;                                                 \
        float nae1 = se1 * pb;                                                  \
        float nao1 = so1 * pl1;                                                 \
        /* pair 0: consumes previous step's shfl result, maximally late */      \
        float t1 = aoRaw * scIn;                                                \
        float se0 = ae0 + t1;                                                   \
        float so0 = ao0 + ae0;                                                  \
        so0 = __fmaf_rn(skA[0], t1, so0);                                       \
        float pl0 = labB[0] ? q1 : q0;                                          \
        float nae0 = se0 * pb;                                                  \
        float nao0 = so0 * pl0;                                                 \
        ae0 = nae0; ae1 = nae1; ae2 = nae2; ae3 = nae3;                         \
        ao0 = nao0; ao1 = nao1; ao2 = nao2; ao3 = nao3;                         \
        aoRaw = aoN;                                                            \
    }

    // Fresh-value normalize (R9 verbatim): full 5-stage prefix-max-with-drift.
#define NORM()                                                                  \
    {                                                                           \
        float mv = fmaxf(fmaxf(fmaxf(ae0, ao0), fmaxf(ae1, ao1)),               \
                         fmaxf(fmaxf(ae2, ao2), fmaxf(ae3, ao3)));              \
        int C = (mv > 0.0f)                                                     \
              ? (R + (int)((__float_as_uint(mv) >> 23) & 255u) - 127)           \
              : CDEAD;                                                          \
        _Pragma("unroll")                                                       \
        for (int o = 1; o < 32; o <<= 1) {                                      \
            int cu = __shfl_up_sync(0xffffffffu, C, o);                         \
            if (lane >= o) C = max(C, cu - DRIFT_T * (o));                      \
        }                                                                       \
        int Rn = C;                                                             \
        int Rp = __shfl_up_sync(0xffffffffu, Rn, 1);                            \
        if (lz) Rp = Rn - 200;                                                  \
        int d = Rp - Rn;                                                        \
        scIn = (d < -127) ? 0.0f : pow2i(min(d, 127));                          \
        int sh = R - Rn;                                                        \
        int sa = max(-127, min(127, sh));                                       \
        int sb = max(-127, min(127, sh - sa));                                  \
        float fa = pow2i(sa), fb = pow2i(sb);                                   \
        ae0 = (ae0*fa)*fb; ae1 = (ae1*fa)*fb; ae2 = (ae2*fa)*fb; ae3 = (ae3*fa)*fb; \
        ao0 = (ao0*fa)*fb; ao1 = (ao1*fa)*fb; ao2 = (ao2*fa)*fb; ao3 = (ao3*fa)*fb; \
        R = Rn;                                                                 \
        aoRaw = __shfl_up_sync(0xffffffffu, ao3, 1);                            \
    }

    NORM();   // establishes scIn / aoRaw for the first window

    const int Tin = input_lengths[b];
    int t = 1;
    // Steady state: R9 shape — preload 8 probs, 8 steps, NORM.
    while (t + 8 <= Tin) {
        float4 q[8];
        #pragma unroll
        for (int j = 0; j < 8; ++j) q[j] = Pw[t + j];
        #pragma unroll
        for (int j = 0; j < 8; ++j) STEP(q[j]);
        t += 8;
        NORM();
    }
    for (; t < Tin; ++t) { float4 q4 = Pw[t]; STEP(q4); }

    // ---- spill finals; lane 0 finalizes this task ----
    AeF[w][p0 + 0] = ae0; AeF[w][p0 + 1] = ae1; AeF[w][p0 + 2] = ae2; AeF[w][p0 + 3] = ae3;
    AoF[w][p0 + 0] = ao0; AoF[w][p0 + 1] = ao1; AoF[w][p0 + 2] = ao2; AoF[w][p0 + 3] = ao3;
    RF[w][lane] = R;
    __syncwarp();

    if (lane == 0 && live) {
        int   Lt = target_lengths[b];
        float v1 = AeF[w][Lt];     int r1 = RF[w][Lt >> 2];
        float v2 = AoF[w][Lt - 1]; int r2 = RF[w][(Lt - 1) >> 2];
        int   Rm = max(r1, r2);
        float w1 = (r1 - Rm < -127) ? 0.0f : pow2i(r1 - Rm);
        float w2 = (r2 - Rm < -127) ? 0.0f : pow2i(r2 - Rm);
        float v  = v1 * w1 + v2 * w2;
        float ll2  = lg2f(v) + (float)Rm;
        float loss = -ll2 * LN2;
        if (!(loss <= 0.5e30f)) loss = 0.0f;   // zero_infinity (also nan/inf)
        g_partials[task] = loss / (float)Lt;
    }
    __syncthreads();

    // ---- fused deterministic reduction (last CTA) ----
    bool isLast = false;
    if (tid == 0) {
        __threadfence();
        int old = atomicAdd(&g_count, 1);
        isLast = (old == (int)gridDim.x - 1);
    }
    if (tid < 32) {
        int last = __shfl_sync(0xffffffffu, isLast ? 1 : 0, 0);
        if (last) {
            float sv = 0.0f;
            for (int j = lane; j < nTasks; j += 32) sv += g_partials[j];
            #pragma unroll
            for (int o = 16; o; o >>= 1) sv += __shfl_down_sync(0xffffffffu, sv, o);
            if (lane == 0) {
                out[0] = sv / (float)nTasks;
                g_count = 0;               // reset for next graph replay
            }
        }
    }
#undef STEP
#undef NORM
}

extern "C" void kernel_launch(void* const* d_in, const int* in_sizes, int n_in,
                              void* d_out, int out_size)
{
    const float* logits  = (const float*)d_in[0];
    const float* blankl  = (const float*)d_in[1];
    const int*   targets = (const int*)d_in[2];
    const int*   in_len  = (const int*)d_in[3];
    const int*   tg_len  = (const int*)d_in[4];

    const int B = in_sizes[3];
    const int T = in_sizes[0] / (B * F_DIM);
    const int S = in_sizes[2] / (B * F_DIM);
    const int nTasks = B * F_DIM;
    const int nblk   = (nTasks + 3) / 4;

    sctc_warp_kernel<<<nblk, 128>>>(logits, blankl, targets, in_len, tg_len,
                                    (float*)d_out, B, T, S, nTasks);
}